// round 2
// baseline (speedup 1.0000x reference)
#include <cuda_runtime.h>
#include <math.h>

#define TT 8192
#define NN 4096
#define LL 64
#define PP 32
#define INDIM 192
#define CHUNK 128
#define NCHUNK 64
#define NBLK_GEMM (32 * 128)

// ---------------- device scratch (no allocations allowed) ----------------
__device__ float g_M[LL * LL];            // M = A + phi_bar @ G
__device__ float g_starts[NCHUNK * LL];   // chunk start states s_{128j}
__device__ float g_xhT[LL * TT];          // xh_seq transposed: [l][t]
__device__ float g_Ut[LL * NN];           // U transposed: [l][n]
__device__ int   g_sel[PP];
__device__ float g_newtemp;
__device__ float g_part[NBLK_GEMM * 2];   // per-block (sum (Y-X)^2, sum Y^2)

// ---------------- packed f32x2 helpers (Blackwell) ----------------
__device__ __forceinline__ unsigned long long pack2(float x) {
    unsigned long long r;
    asm("mov.b64 %0, {%1, %1};" : "=l"(r) : "f"(x));
    return r;
}
__device__ __forceinline__ void fma2(unsigned long long& d,
                                     unsigned long long a,
                                     unsigned long long b) {
    asm("fma.rn.f32x2 %0, %1, %2, %0;" : "+l"(d) : "l"(a), "l"(b));
}
__device__ __forceinline__ float2 u2f(unsigned long long v) {
    float2 f;
    asm("mov.b64 {%0, %1}, %2;" : "=f"(f.x), "=f"(f.y) : "l"(v));
    return f;
}

// ============================================================================
// Kernel A (1 block, 256 threads): argmax -> sel/new_temp, build M,
// xh0 = U^T x0, Mc = M^128 (7 squarings), 64 chunk-start vectors.
// ============================================================================
__global__ __launch_bounds__(256) void kA(const float* __restrict__ Xtr,
                                          const float* __restrict__ temp,
                                          const float* __restrict__ phi,
                                          const float* __restrict__ Atil,
                                          const float* __restrict__ U,
                                          const float* __restrict__ logits) {
    __shared__ __align__(16) float sM[LL * LL];
    __shared__ __align__(16) float sQ[LL * LL];
    __shared__ float sV[LL];
    __shared__ float sPart[16 * LL];
    __shared__ int   ssel[PP];
    const int tid = threadIdx.x;

    // argmax per logits row (first max, matches jnp.argmax)
    if (tid < PP) {
        const float* row = logits + tid * INDIM;
        float best = row[0];
        int bi = 0;
        for (int j = 1; j < INDIM; j++) {
            float v = row[j];
            if (v > best) { best = v; bi = j; }
        }
        ssel[tid] = bi;
        g_sel[tid] = bi;
    }
    if (tid == 0) g_newtemp = fmaxf(0.01f, temp[0] * 0.999f);

    // M = A_tilde + phi_bar @ G (clipped gather)
    for (int idx = tid; idx < LL * LL; idx += 256) sM[idx] = Atil[idx];
    __syncthreads();
    if (tid < LL) {
        float* mrow = &sM[tid * LL];
        for (int p = 0; p < PP; p++) {
            int j = ssel[p];
            if (j > LL - 1) j = LL - 1;          // mode='clip'
            mrow[j] += phi[p * LL + tid];        // phi_bar[i][p] = phi_t[p][i]
        }
    }
    __syncthreads();
    for (int idx = tid; idx < LL * LL; idx += 256) g_M[idx] = sM[idx];

    // xh0 = U^T x0  (x0 = first row of X_train)
    {
        const int lq = tid & 15, g = tid >> 4;
        float4 acc = make_float4(0.f, 0.f, 0.f, 0.f);
        const float4* U4 = (const float4*)U;
        const int nbeg = g * 256;
        for (int n = nbeg; n < nbeg + 256; n++) {
            float4 u = U4[n * 16 + lq];
            float x = Xtr[n];
            acc.x += u.x * x; acc.y += u.y * x;
            acc.z += u.z * x; acc.w += u.w * x;
        }
        sPart[g * LL + 4 * lq + 0] = acc.x;
        sPart[g * LL + 4 * lq + 1] = acc.y;
        sPart[g * LL + 4 * lq + 2] = acc.z;
        sPart[g * LL + 4 * lq + 3] = acc.w;
    }
    __syncthreads();
    if (tid < LL) {
        float s = 0.f;
        for (int g = 0; g < 16; g++) s += sPart[g * LL + tid];  // fixed order
        sV[tid] = s;
        g_starts[tid] = s;   // chunk 0 start = xh0
    }
    __syncthreads();

    // Mc = M^128 via 7 squarings (f32x2 FMA, 4x4 tile per thread)
    float* src = sM;
    float* dst = sQ;
    const int ti = (tid >> 4) << 2;
    const int tj = (tid & 15) << 2;
    for (int s = 0; s < 7; s++) {
        unsigned long long o00 = 0, o01 = 0, o10 = 0, o11 = 0;
        unsigned long long o20 = 0, o21 = 0, o30 = 0, o31 = 0;
        #pragma unroll 8
        for (int k = 0; k < LL; k++) {
            ulonglong2 bp = *(const ulonglong2*)&src[k * LL + tj];
            unsigned long long a0 = pack2(src[(ti + 0) * LL + k]);
            unsigned long long a1 = pack2(src[(ti + 1) * LL + k]);
            unsigned long long a2 = pack2(src[(ti + 2) * LL + k]);
            unsigned long long a3 = pack2(src[(ti + 3) * LL + k]);
            fma2(o00, a0, bp.x); fma2(o01, a0, bp.y);
            fma2(o10, a1, bp.x); fma2(o11, a1, bp.y);
            fma2(o20, a2, bp.x); fma2(o21, a2, bp.y);
            fma2(o30, a3, bp.x); fma2(o31, a3, bp.y);
        }
        __syncthreads();
        *(unsigned long long*)&dst[(ti + 0) * LL + tj]     = o00;
        *(unsigned long long*)&dst[(ti + 0) * LL + tj + 2] = o01;
        *(unsigned long long*)&dst[(ti + 1) * LL + tj]     = o10;
        *(unsigned long long*)&dst[(ti + 1) * LL + tj + 2] = o11;
        *(unsigned long long*)&dst[(ti + 2) * LL + tj]     = o20;
        *(unsigned long long*)&dst[(ti + 2) * LL + tj + 2] = o21;
        *(unsigned long long*)&dst[(ti + 3) * LL + tj]     = o30;
        *(unsigned long long*)&dst[(ti + 3) * LL + tj + 2] = o31;
        __syncthreads();
        float* t = src; src = dst; dst = t;
    }
    // src now holds Mc = M^128

    // sequential chunk-start prefix: v_j = Mc @ v_{j-1}
    {
        const int i = tid & 63, q = tid >> 6;   // 4-way k split
        float mr[16];
        #pragma unroll
        for (int kk = 0; kk < 16; kk++) mr[kk] = src[i * LL + q * 16 + kk];
        for (int j = 1; j < NCHUNK; j++) {
            float a0 = 0.f, a1 = 0.f, a2 = 0.f, a3 = 0.f;
            #pragma unroll
            for (int kk = 0; kk < 16; kk += 4) {
                a0 += mr[kk + 0] * sV[q * 16 + kk + 0];
                a1 += mr[kk + 1] * sV[q * 16 + kk + 1];
                a2 += mr[kk + 2] * sV[q * 16 + kk + 2];
                a3 += mr[kk + 3] * sV[q * 16 + kk + 3];
            }
            sPart[q * LL + i] = (a0 + a1) + (a2 + a3);
            __syncthreads();
            if (tid < LL) {
                float nv = (sPart[i] + sPart[LL + i]) +
                           (sPart[2 * LL + i] + sPart[3 * LL + i]);
                sV[i] = nv;
                g_starts[j * LL + i] = nv;
            }
            __syncthreads();
        }
    }
}

// ============================================================================
// Kernel T: transpose U (N,L) -> g_Ut (L,N)
// ============================================================================
__global__ __launch_bounds__(256) void kT(const float* __restrict__ U) {
    __shared__ float tile[32][33];
    const int l0 = blockIdx.x * 32;
    const int n0 = blockIdx.y * 32;
    const int x = threadIdx.x & 31;
    const int y0 = threadIdx.x >> 5;
    #pragma unroll
    for (int r = y0; r < 32; r += 8)
        tile[r][x] = U[(size_t)(n0 + r) * LL + l0 + x];
    __syncthreads();
    #pragma unroll
    for (int r = y0; r < 32; r += 8)
        g_xhT[0] = g_xhT[0];  // no-op placeholder removed below
    #pragma unroll
    for (int r = y0; r < 32; r += 8)
        g_Ut[(size_t)(l0 + r) * NN + n0 + x] = tile[x][r];
}

// ============================================================================
// Kernel B (64 blocks, 128 threads): chunk j runs 128 sequential matvecs
// from g_starts[j], emitting xh transposed into g_xhT.
// ============================================================================
__global__ __launch_bounds__(128) void kB() {
    __shared__ float sv[LL];
    __shared__ float sp[2 * LL];
    __shared__ float sbuf[LL * 33];
    const int tid = threadIdx.x;
    const int i = tid & 63, q = tid >> 6;   // 2-way k split
    const int j = blockIdx.x;

    float mr[32];
    #pragma unroll
    for (int kk = 0; kk < 32; kk++) mr[kk] = g_M[i * LL + q * 32 + kk];
    if (tid < LL) sv[tid] = g_starts[j * LL + tid];
    __syncthreads();

    const int tbase = j * CHUNK;
    for (int h = 0; h < 4; h++) {
        for (int c = 0; c < 32; c++) {
            float a0 = 0.f, a1 = 0.f, a2 = 0.f, a3 = 0.f;
            #pragma unroll
            for (int kk = 0; kk < 32; kk += 4) {
                a0 += mr[kk + 0] * sv[q * 32 + kk + 0];
                a1 += mr[kk + 1] * sv[q * 32 + kk + 1];
                a2 += mr[kk + 2] * sv[q * 32 + kk + 2];
                a3 += mr[kk + 3] * sv[q * 32 + kk + 3];
            }
            sp[q * LL + i] = (a0 + a1) + (a2 + a3);
            __syncthreads();
            if (q == 0) {
                float nv = sp[i] + sp[LL + i];
                sv[i] = nv;
                sbuf[i * 33 + c] = nv;
            }
            __syncthreads();
        }
        for (int idx = tid; idx < LL * 32; idx += 128) {
            int r = idx >> 5, cc = idx & 31;
            g_xhT[(size_t)r * TT + tbase + h * 32 + cc] = sbuf[r * 33 + cc];
        }
        __syncthreads();
    }
}

// ============================================================================
// Kernel C: X_rec = xh_seq @ U^T, 64t x 128n tiles, K=64, f32x2 FMA,
// fused store + residual/norm partials.
// ============================================================================
__global__ __launch_bounds__(256) void kC(const float* __restrict__ Y,
                                          float* __restrict__ out) {
    __shared__ __align__(16) float smem[LL * 64 + LL * 128];  // 48KB
    float* sA = smem;            // [k][t], 64x64
    float* sB = smem + LL * 64;  // [k][n], 64x128

    const int tid = threadIdx.x;
    const int t0 = blockIdx.y * 64;
    const int n0 = blockIdx.x * 128;

    for (int idx = tid; idx < 1024; idx += 256) {
        int k = idx >> 4, iq = idx & 15;
        *(float4*)&sA[k * 64 + iq * 4] =
            *(const float4*)&g_xhT[(size_t)k * TT + t0 + iq * 4];
    }
    for (int idx = tid; idx < 2048; idx += 256) {
        int k = idx >> 5, jq = idx & 31;
        *(float4*)&sB[k * 128 + jq * 4] =
            *(const float4*)&g_Ut[(size_t)k * NN + n0 + jq * 4];
    }
    __syncthreads();

    const int tx = tid & 31, ty = tid >> 5;
    const int i0 = ty * 8;        // 8 t-rows as 4 f32x2 pairs
    const int j0 = tx * 4;        // 4 consecutive n-cols

    unsigned long long acc[4][4];
    #pragma unroll
    for (int a = 0; a < 4; a++)
        #pragma unroll
        for (int b = 0; b < 4; b++) acc[a][b] = 0ull;

    #pragma unroll 8
    for (int k = 0; k < LL; k++) {
        ulonglong2 a01 = *(const ulonglong2*)&sA[k * 64 + i0];
        ulonglong2 a23 = *(const ulonglong2*)&sA[k * 64 + i0 + 4];
        float4 b = *(const float4*)&sB[k * 128 + j0];
        unsigned long long b0 = pack2(b.x), b1 = pack2(b.y);
        unsigned long long b2 = pack2(b.z), b3 = pack2(b.w);
        fma2(acc[0][0], a01.x, b0); fma2(acc[0][1], a01.x, b1);
        fma2(acc[0][2], a01.x, b2); fma2(acc[0][3], a01.x, b3);
        fma2(acc[1][0], a01.y, b0); fma2(acc[1][1], a01.y, b1);
        fma2(acc[1][2], a01.y, b2); fma2(acc[1][3], a01.y, b3);
        fma2(acc[2][0], a23.x, b0); fma2(acc[2][1], a23.x, b1);
        fma2(acc[2][2], a23.x, b2); fma2(acc[2][3], a23.x, b3);
        fma2(acc[3][0], a23.y, b0); fma2(acc[3][1], a23.y, b1);
        fma2(acc[3][2], a23.y, b2); fma2(acc[3][3], a23.y, b3);
    }

    // Epilogue: coalesced float4 stores + fused residual/norm accumulation.
    float s1 = 0.f, s2 = 0.f;
    #pragma unroll
    for (int a = 0; a < 4; a++) {
        float2 c0 = u2f(acc[a][0]), c1 = u2f(acc[a][1]);
        float2 c2 = u2f(acc[a][2]), c3 = u2f(acc[a][3]);
        size_t ox = (size_t)(t0 + i0 + 2 * a) * NN + n0 + j0;
        size_t oy = ox + NN;
        float4 vx = make_float4(c0.x, c1.x, c2.x, c3.x);
        float4 vy = make_float4(c0.y, c1.y, c2.y, c3.y);
        *(float4*)&out[ox] = vx;
        *(float4*)&out[oy] = vy;
        float4 y0 = *(const float4*)&Y[ox];
        float4 y1 = *(const float4*)&Y[oy];
        float d;
        d = y0.x - vx.x; s1 += d * d; s2 += y0.x * y0.x;
        d = y0.y - vx.y; s1 += d * d; s2 += y0.y * y0.y;
        d = y0.z - vx.z; s1 += d * d; s2 += y0.z * y0.z;
        d = y0.w - vx.w; s1 += d * d; s2 += y0.w * y0.w;
        d = y1.x - vy.x; s1 += d * d; s2 += y1.x * y1.x;
        d = y1.y - vy.y; s1 += d * d; s2 += y1.y * y1.y;
        d = y1.z - vy.z; s1 += d * d; s2 += y1.z * y1.z;
        d = y1.w - vy.w; s1 += d * d; s2 += y1.w * y1.w;
    }

    __syncthreads();             // done with sA/sB
    float* r1 = smem;
    float* r2 = smem + 256;
    r1[tid] = s1; r2[tid] = s2;
    __syncthreads();
    #pragma unroll
    for (int s = 128; s > 0; s >>= 1) {
        if (tid < s) { r1[tid] += r1[tid + s]; r2[tid] += r2[tid + s]; }
        __syncthreads();
    }
    if (tid == 0) {
        int bid = blockIdx.y * 32 + blockIdx.x;
        g_part[bid * 2]     = r1[0];
        g_part[bid * 2 + 1] = r2[0];
    }
}

// ============================================================================
// Kernel D: final reduction -> err, new_temp, selected_idx tail of output.
// ============================================================================
__global__ __launch_bounds__(256) void kD(float* __restrict__ out, int has_tail) {
    __shared__ float r1[256], r2[256];
    const int tid = threadIdx.x;
    float s1 = 0.f, s2 = 0.f;
    for (int i = tid; i < NBLK_GEMM; i += 256) {
        s1 += g_part[2 * i];
        s2 += g_part[2 * i + 1];
    }
    r1[tid] = s1; r2[tid] = s2;
    __syncthreads();
    #pragma unroll
    for (int s = 128; s > 0; s >>= 1) {
        if (tid < s) { r1[tid] += r1[tid + s]; r2[tid] += r2[tid + s]; }
        __syncthreads();
    }
    if (!has_tail) return;
    const size_t base = (size_t)TT * NN;
    if (tid == 0) {
        out[base]     = sqrtf(r1[0] / r2[0]);
        out[base + 1] = g_newtemp;
    }
    if (tid < PP) out[base + 2 + tid] = (float)g_sel[tid];
}

extern "C" void kernel_launch(void* const* d_in, const int* in_sizes, int n_in,
                              void* d_out, int out_size) {
    const float* Xtil   = (const float*)d_in[0];  (void)Xtil;
    const float* Xtr    = (const float*)d_in[1];
    const float* Ytr    = (const float*)d_in[2];
    const float* temp   = (const float*)d_in[3];
    const float* phi    = (const float*)d_in[4];
    const float* Atil   = (const float*)d_in[5];
    const float* U      = (const float*)d_in[6];
    const float* logits = (const float*)d_in[7];
    float* out = (float*)d_out;
    const long long total = (long long)TT * NN + 2 + PP;
    const int has_tail = ((long long)out_size >= total) ? 1 : 0;

    kA<<<1, 256>>>(Xtr, temp, phi, Atil, U, logits);
    kT<<<dim3(2, 128), 256>>>(U);
    kB<<<NCHUNK, 128>>>();
    kC<<<dim3(32, 128), 256>>>(Ytr, out);
    kD<<<1, 256>>>(out, has_tail);
}